// round 17
// baseline (speedup 1.0000x reference)
#include <cuda_runtime.h>
#include <cstdint>

// Problem constants (fixed by setup_inputs)
#define B_    4
#define NC    4096      // coarse points per batch
#define MF    16384     // fine points per batch
#define CIN   384
#define COUT  192
#define NTOT  (B_*NC)   // 16384
#define MTOT  (B_*MF)   // 65536

// Scratch (static device globals; allocation-free)
__device__ float g_h[NTOT * COUT];      // branch-2 features at coarse points
__device__ int   g_idx[MTOT * 3];       // 3-NN indices (global coarse index)
__device__ float g_wgt[MTOT * 3];       // 3-NN normalized inverse-distance weights
__device__ float g_w2p[CIN * COUT];     // gamma-folded weights
__device__ float g_w1p[COUT * COUT];
__device__ float g_b2p[COUT];           // beta-folded biases
__device__ float g_b1p[COUT];
__device__ float g_cs2[COUT];           // colsum of gamma-folded w2
__device__ float g_cs1[COUT];           // colsum of gamma-folded w1

// ---------------------------------------------------------------------------
// Fold LN gamma into W, LN beta into bias; column sums of folded W.
// grid = CIN + COUT + 4 blocks of 192 threads
// ---------------------------------------------------------------------------
__global__ void prep_kernel(const float* __restrict__ w2, const float* __restrict__ ln2_g,
                            const float* __restrict__ ln2_b, const float* __restrict__ b2,
                            const float* __restrict__ w1, const float* __restrict__ ln1_g,
                            const float* __restrict__ ln1_b, const float* __restrict__ b1)
{
    int bid = blockIdx.x;
    int n = threadIdx.x;             // 0..191
    if (bid < CIN) {
        g_w2p[bid * COUT + n] = ln2_g[bid] * w2[bid * COUT + n];
    } else if (bid < CIN + COUT) {
        int k = bid - CIN;
        g_w1p[k * COUT + n] = ln1_g[k] * w1[k * COUT + n];
    } else if (bid == CIN + COUT) {
        float s = b2[n];
        for (int k = 0; k < CIN; k++) s = fmaf(ln2_b[k], w2[k * COUT + n], s);
        g_b2p[n] = s;
    } else if (bid == CIN + COUT + 1) {
        float s = b1[n];
        for (int k = 0; k < COUT; k++) s = fmaf(ln1_b[k], w1[k * COUT + n], s);
        g_b1p[n] = s;
    } else if (bid == CIN + COUT + 2) {
        float s = 0.f;
        for (int k = 0; k < CIN; k++) s = fmaf(ln2_g[k], w2[k * COUT + n], s);
        g_cs2[n] = s;
    } else {
        float s = 0.f;
        for (int k = 0; k < COUT; k++) s = fmaf(ln1_g[k], w1[k * COUT + n], s);
        g_cs1[n] = s;
    }
}

// ---------------------------------------------------------------------------
// Brute-force 3-NN per batch segment. Coarse xyz in shared (SoA, 48KB).
// ---------------------------------------------------------------------------
__global__ void knn_kernel(const float* __restrict__ cxyz,   // [NTOT,3] coarse
                           const float* __restrict__ qxyz)   // [MTOT,3] fine
{
    extern __shared__ float smem[];
    float* sx = smem;
    float* sy = smem + NC;
    float* sz = smem + 2 * NC;

    int bidx  = blockIdx.x >> 6;
    int chunk = blockIdx.x & 63;
    const float* cb = cxyz + (long)bidx * NC * 3;
    for (int i = threadIdx.x; i < NC; i += 256) {
        sx[i] = cb[i * 3 + 0];
        sy[i] = cb[i * 3 + 1];
        sz[i] = cb[i * 3 + 2];
    }
    __syncthreads();

    int q = bidx * MF + chunk * 256 + threadIdx.x;
    float qx = qxyz[q * 3 + 0], qy = qxyz[q * 3 + 1], qz = qxyz[q * 3 + 2];

    float b0 = 1e30f, b1 = 1e30f, b2 = 1e30f;
    int   i0 = 0, i1 = 0, i2 = 0;

#pragma unroll 8
    for (int j = 0; j < NC; j++) {
        float dx = qx - sx[j];
        float dy = qy - sy[j];
        float dz = qz - sz[j];
        float d  = fmaf(dz, dz, fmaf(dy, dy, dx * dx));
        if (d < b2) {
            if (d < b1) {
                b2 = b1; i2 = i1;
                if (d < b0) { b1 = b0; i1 = i0; b0 = d; i0 = j; }
                else        { b1 = d;  i1 = j; }
            } else { b2 = d; i2 = j; }
        }
    }

    float r0 = 1.0f / (sqrtf(b0) + 1e-8f);
    float r1 = 1.0f / (sqrtf(b1) + 1e-8f);
    float r2 = 1.0f / (sqrtf(b2) + 1e-8f);
    float rs = 1.0f / (r0 + r1 + r2);

    g_idx[q * 3 + 0] = bidx * NC + i0;
    g_idx[q * 3 + 1] = bidx * NC + i1;
    g_idx[q * 3 + 2] = bidx * NC + i2;
    g_wgt[q * 3 + 0] = r0 * rs;
    g_wgt[q * 3 + 1] = r1 * rs;
    g_wgt[q * 3 + 2] = r2 * rs;
}

// ---------------------------------------------------------------------------
// Fused GEMM with in-kernel LN (affine identity):
//   out = rstd * (x@W' - mu*colsum(W')) + b'  (+ optional 3-NN interp)
// Champion 128x64/BK16/8x4 core unchanged; A streamed RAW, per-row (s,ss)
// accumulated by the loader threads (each covers exactly half a row),
// combined via smem, normalization applied in the epilogue.
// ---------------------------------------------------------------------------
template<int K, bool INTERP>
__global__ __launch_bounds__(256)
void gemm_kernel(const float* __restrict__ A,
                 const float* __restrict__ W, const float* __restrict__ bias,
                 const float* __restrict__ csum, float* __restrict__ C)
{
    constexpr int KT = K / 16;
    __shared__ float As[2][16][132];   // [stage][k][m] (transposed, padded)
    __shared__ float Bs[2][16][64];    // [stage][k][n]
    __shared__ float2 sstat[256];      // per-loader-thread (s, ss)

    int t  = threadIdx.x;
    int tx = t & 15, ty = t >> 4;
    int m0 = blockIdx.y * 128;
    int n0 = blockIdx.x * 64;

    // A loader: thread -> (row, 8-col group); 2 threads cover a full row over KT tiles
    int arow  = t >> 1;
    int acol8 = (t & 1) * 8;
    const float* Arow = A + (long)(m0 + arow) * K;

    // B loader
    int brow = t >> 4;
    int bcol = (t & 15) * 4;

    float4 pa0, pa1, pb;
    float s_acc = 0.f, ss_acc = 0.f;

    // prologue: tile 0
    pa0 = *(const float4*)(Arow + acol8);
    pa1 = *(const float4*)(Arow + acol8 + 4);
    pb  = *(const float4*)(W + (long)brow * COUT + n0 + bcol);
    {
        float vv[8] = {pa0.x, pa0.y, pa0.z, pa0.w, pa1.x, pa1.y, pa1.z, pa1.w};
#pragma unroll
        for (int j = 0; j < 8; j++) {
            As[0][acol8 + j][arow] = vv[j];
            s_acc  += vv[j];
            ss_acc += vv[j] * vv[j];
        }
    }
    *(float4*)&Bs[0][brow][bcol] = pb;
    __syncthreads();

    float acc[8][4] = {};
    int s = 0;

#pragma unroll 1
    for (int kt = 0; kt < KT; kt++) {
        int k0n = (kt + 1) * 16;
        if (kt + 1 < KT) {
            pa0 = *(const float4*)(Arow + k0n + acol8);
            pa1 = *(const float4*)(Arow + k0n + acol8 + 4);
            pb  = *(const float4*)(W + (long)(k0n + brow) * COUT + n0 + bcol);
        }
#pragma unroll
        for (int k = 0; k < 16; k++) {
            float4 a0 = *(const float4*)&As[s][k][ty * 8];
            float4 a1 = *(const float4*)&As[s][k][ty * 8 + 4];
            float4 b  = *(const float4*)&Bs[s][k][tx * 4];
            float ar[8] = {a0.x, a0.y, a0.z, a0.w, a1.x, a1.y, a1.z, a1.w};
            float br[4] = {b.x, b.y, b.z, b.w};
#pragma unroll
            for (int i = 0; i < 8; i++)
#pragma unroll
                for (int j = 0; j < 4; j++)
                    acc[i][j] = fmaf(ar[i], br[j], acc[i][j]);
        }
        if (kt + 1 < KT) {
            int ns = s ^ 1;
            float vv[8] = {pa0.x, pa0.y, pa0.z, pa0.w, pa1.x, pa1.y, pa1.z, pa1.w};
#pragma unroll
            for (int j = 0; j < 8; j++) {
                As[ns][acol8 + j][arow] = vv[j];
                s_acc  += vv[j];
                ss_acc += vv[j] * vv[j];
            }
            *(float4*)&Bs[ns][brow][bcol] = pb;
            __syncthreads();
            s = ns;
        }
    }

    // publish per-half-row sums, then combine in epilogue
    sstat[t] = make_float2(s_acc, ss_acc);
    __syncthreads();

    float bb[4], cs[4];
#pragma unroll
    for (int j = 0; j < 4; j++) {
        bb[j] = bias[n0 + tx * 4 + j];
        cs[j] = csum[n0 + tx * 4 + j];
    }

#pragma unroll
    for (int i = 0; i < 8; i++) {
        int r   = ty * 8 + i;           // row within CTA
        int row = m0 + r;
        float2 p0 = sstat[2 * r];
        float2 p1 = sstat[2 * r + 1];
        float sum  = p0.x + p1.x;
        float sums = p0.y + p1.y;
        float mu   = sum * (1.0f / K);
        float var  = sums * (1.0f / K) - mu * mu;
        float rstd = rsqrtf(var + 1e-5f);

        float o0 = (acc[i][0] - mu * cs[0]) * rstd + bb[0];
        float o1 = (acc[i][1] - mu * cs[1]) * rstd + bb[1];
        float o2 = (acc[i][2] - mu * cs[2]) * rstd + bb[2];
        float o3 = (acc[i][3] - mu * cs[3]) * rstd + bb[3];
        if (INTERP) {
            int   j0 = g_idx[row * 3 + 0], j1 = g_idx[row * 3 + 1], j2 = g_idx[row * 3 + 2];
            float w0 = g_wgt[row * 3 + 0], w1 = g_wgt[row * 3 + 1], w2 = g_wgt[row * 3 + 2];
            int coff = n0 + tx * 4;
            float4 h0 = *(const float4*)(g_h + (long)j0 * COUT + coff);
            float4 h1 = *(const float4*)(g_h + (long)j1 * COUT + coff);
            float4 h2 = *(const float4*)(g_h + (long)j2 * COUT + coff);
            o0 += w0 * h0.x + w1 * h1.x + w2 * h2.x;
            o1 += w0 * h0.y + w1 * h1.y + w2 * h2.y;
            o2 += w0 * h0.z + w1 * h1.z + w2 * h2.z;
            o3 += w0 * h0.w + w1 * h1.w + w2 * h2.w;
        }
        *(float4*)(C + (long)row * COUT + n0 + tx * 4) = make_float4(o0, o1, o2, o3);
    }
}

// ---------------------------------------------------------------------------
// Tail: copy support_xyz and support_offset (value-cast to float) into d_out
// ---------------------------------------------------------------------------
__global__ void tail_kernel(const float* __restrict__ sxyz, const int* __restrict__ soff,
                            float* __restrict__ out)
{
    int i = blockIdx.x * 256 + threadIdx.x;
    if (i < MTOT * 3) out[MTOT * COUT + i] = sxyz[i];
    if (i < B_)       out[MTOT * COUT + MTOT * 3 + i] = (float)soff[i];
}

// ---------------------------------------------------------------------------
extern "C" void kernel_launch(void* const* d_in, const int* in_sizes, int n_in,
                              void* d_out, int out_size)
{
    const float* feats  = (const float*)d_in[0];
    const float* xyz    = (const float*)d_in[1];
    const float* sxyz   = (const float*)d_in[2];
    const float* sfeats = (const float*)d_in[3];
    const int*   soff   = (const int*)  d_in[5];
    const float* ln1_g  = (const float*)d_in[6];
    const float* ln1_b  = (const float*)d_in[7];
    const float* w1     = (const float*)d_in[8];
    const float* b1     = (const float*)d_in[9];
    const float* ln2_g  = (const float*)d_in[10];
    const float* ln2_b  = (const float*)d_in[11];
    const float* w2     = (const float*)d_in[12];
    const float* b2     = (const float*)d_in[13];
    float* out = (float*)d_out;

    static cudaStream_t s2 = nullptr, s3 = nullptr;
    static cudaEvent_t ev_fork = nullptr, ev_j2 = nullptr, ev_prep = nullptr;
    if (!s2) {
        cudaStreamCreateWithFlags(&s2, cudaStreamNonBlocking);
        cudaStreamCreateWithFlags(&s3, cudaStreamNonBlocking);
        cudaEventCreateWithFlags(&ev_fork, cudaEventDisableTiming);
        cudaEventCreateWithFlags(&ev_j2, cudaEventDisableTiming);
        cudaEventCreateWithFlags(&ev_prep, cudaEventDisableTiming);
    }

    float *p_h, *p_w2p, *p_w1p, *p_b2p, *p_b1p, *p_cs2, *p_cs1;
    cudaGetSymbolAddress((void**)&p_h,   g_h);
    cudaGetSymbolAddress((void**)&p_w2p, g_w2p);
    cudaGetSymbolAddress((void**)&p_w1p, g_w1p);
    cudaGetSymbolAddress((void**)&p_b2p, g_b2p);
    cudaGetSymbolAddress((void**)&p_b1p, g_b1p);
    cudaGetSymbolAddress((void**)&p_cs2, g_cs2);
    cudaGetSymbolAddress((void**)&p_cs1, g_cs1);

    // fork
    cudaEventRecord(ev_fork, 0);
    cudaStreamWaitEvent(s2, ev_fork, 0);
    cudaStreamWaitEvent(s3, ev_fork, 0);

    // s2: kNN + tail (independent of GEMM chain)
    knn_kernel<<<MTOT / 256, 256, 3 * NC * sizeof(float), s2>>>(xyz, sxyz);
    tail_kernel<<<(MTOT * 3 + 255) / 256, 256, 0, s2>>>(sxyz, soff, out);
    cudaEventRecord(ev_j2, s2);

    // s3: weight prep (only dependency of the GEMMs besides inputs)
    prep_kernel<<<CIN + COUT + 4, COUT, 0, s3>>>(w2, ln2_g, ln2_b, b2, w1, ln1_g, ln1_b, b1);
    cudaEventRecord(ev_prep, s3);

    // main: gemm2 (LN computed in-kernel)
    cudaStreamWaitEvent(0, ev_prep, 0);
    {
        dim3 grid(COUT / 64, NTOT / 128);
        gemm_kernel<CIN, false><<<grid, 256>>>(feats, p_w2p, p_b2p, p_cs2, p_h);
    }

    // join kNN, then gemm1 with fused interp epilogue
    cudaStreamWaitEvent(0, ev_j2, 0);
    {
        dim3 grid(COUT / 64, MTOT / 128);
        gemm_kernel<COUT, true><<<grid, 256>>>(sfeats, p_w1p, p_b1p, p_cs1, out);
    }
}